// round 11
// baseline (speedup 1.0000x reference)
#include <cuda_runtime.h>
#include <math.h>

// ---------------------------------------------------------------------------
// BalancedFrequencyAttention, collapsed form (see R2 derivation):
//   gap[b,c] = sum_{h,n} x[b,c,h,n] * w(h,n)
//   w(h,n)   = c0 + [h>=80] * (0.4/48000) * g_{(h-80)%3}(n),  period-12 in n
//   att      = sigmoid(gap @ w1^T @ w2^T);  out = x * att[:,:,None,None]
//
// R10: reduce now reads CONTIGUOUS 40-row stripes per block (better HBM page
// locality than the old class-strided rows). The class weight is factored out
// of the loop entirely: per-class raw sums in 3 rotating float4 accumulators
// (class rotation is compile-time, period 3), weights applied once at the end.
// mlp / scale / PDL chain unchanged from R9 (measured at roofline).
// ---------------------------------------------------------------------------

#define N_CH        1024      // B*C
#define Q_PER_CH    24000     // 200*480/4 float4 per channel
#define BLKS_PER_CH 5
#define TOTAL_Q4    (N_CH * Q_PER_CH)        // 24,576,000 = 48000 * 512

__device__ float d_part[N_CH * BLKS_PER_CH];
__device__ float d_att[N_CH];

// ---- Kernel 1: weighted reduction, contiguous stripes, class accumulators ----
__global__ __launch_bounds__(256, 8) void reduce_kernel(const float4* __restrict__ x) {
    const float c0  = 8.838834764831843e-06f;   // 0.6/sqrt(2)/48000
    const float inv = 8.333333333333334e-06f;   // 0.4/48000
    const float PI  = 3.14159265358979323846f;

    const int blk = blockIdx.x;
    const int ch  = blk / BLKS_PER_CH;
    const int s   = blk - ch * BLKS_PER_CH;     // stripe: rows 40s .. 40s+39

    const int t    = threadIdx.x;
    const int c4   = t & 127;          // float4 column (0..119 active)
    const int r    = t >> 7;           // parity row within stripe (0/1)
    const bool act = (c4 < 120);

    const float4* p = x + (size_t)ch * Q_PER_CH + (size_t)(40 * s + r) * 120 + c4;

    float acc;
    if (s < 2) {
        // Low stripes: uniform weight c0. Plain contiguous sum.
        float4 a = make_float4(0.f, 0.f, 0.f, 0.f);
        if (act) {
            #pragma unroll 5
            for (int i = 0; i < 20; i++) {
                float4 v = __ldcs(p); p += 240;   // advance 2 rows
                a.x += v.x; a.y += v.y; a.z += v.z; a.w += v.w;
            }
        }
        acc = c0 * ((a.x + a.y) + (a.z + a.w));
    } else {
        // High stripes: rows h = 40s + r + 2i, class cls(i) = (b0 + 2i) % 3,
        // b0 = (40s - 80 + r) % 3 (warp-uniform). Per group of 3 iterations the
        // classes are (b0, b0+2, b0+1) — accumulate raw sums into A, B, C.
        float4 A = make_float4(0.f, 0.f, 0.f, 0.f), B = A, C = A;
        if (act) {
            #pragma unroll 1
            for (int g = 0; g < 6; g++) {        // 18 rows-per-parity... 18 iters
                float4 v0 = __ldcs(p);
                float4 v1 = __ldcs(p + 240);
                float4 v2 = __ldcs(p + 480);
                p += 720;
                A.x += v0.x; A.y += v0.y; A.z += v0.z; A.w += v0.w;
                B.x += v1.x; B.y += v1.y; B.z += v1.z; B.w += v1.w;
                C.x += v2.x; C.y += v2.y; C.z += v2.z; C.w += v2.w;
            }
            {   // tail: i = 18 (class b0 -> A), i = 19 (class b0+2 -> B)
                float4 v0 = __ldcs(p);
                float4 v1 = __ldcs(p + 240);
                A.x += v0.x; A.y += v0.y; A.z += v0.z; A.w += v0.w;
                B.x += v1.x; B.y += v1.y; B.z += v1.z; B.w += v1.w;
            }
        }
        // Map accumulators to absolute classes: A->b0, B->(b0+2)%3, C->(b0+1)%3
        const int b0 = (40 * s - 80 + r) % 3;
        float4 a0, a1, a2;
        if (b0 == 0)      { a0 = A; a2 = B; a1 = C; }
        else if (b0 == 1) { a1 = A; a0 = B; a2 = C; }
        else              { a2 = A; a1 = B; a0 = C; }

        // Per-component class weights (computed once, post-loop).
        const int n0 = c4 << 2;
        acc = 0.f;
        #pragma unroll
        for (int e = 0; e < 4; e++) {
            float a  = (float)(2 * ((n0 + e) % 12) + 1);
            float w0 = c0 + inv * (cosf(a * (PI / 12.f)) + cosf(a * (PI / 3.f)));
            float w1 = c0 + inv * (cosf(a * (PI / 6.f))  + cosf(a * (5.f * PI / 12.f)));
            float w2 = c0 + inv * cosf(a * (PI / 4.f));
            const float* pa0 = &a0.x; const float* pa1 = &a1.x; const float* pa2 = &a2.x;
            acc += pa0[e] * w0 + pa1[e] * w1 + pa2[e] * w2;
        }
    }

    __shared__ float wsum[8];
    #pragma unroll
    for (int o = 16; o; o >>= 1) acc += __shfl_xor_sync(0xffffffffu, acc, o);
    if ((t & 31) == 0) wsum[t >> 5] = acc;
    __syncthreads();
    if (t < 8) {
        float v = wsum[t];
        #pragma unroll
        for (int o = 4; o; o >>= 1) v += __shfl_xor_sync(0xffu, v, o);
        if (t == 0) { d_part[blk] = v; __threadfence(); }
    }
    __syncthreads();
    cudaTriggerProgrammaticLaunchCompletion();   // release mlp at last store
}

// ---- Kernel 2: fold partials + tiny MLP + sigmoid (PDL) ----------------------
__global__ __launch_bounds__(256) void mlp_kernel(const float* __restrict__ w1,
                                                  const float* __restrict__ w2) {
    __shared__ float sg[1024];
    __shared__ float sw1[32][129];   // padded: conflict-free column reads
    __shared__ float sw2[128][33];
    __shared__ float st1[256];
    int tid = threadIdx.x;

    // Independent of d_part: overlaps reduce_kernel execution.
    for (int i = tid; i < 4096; i += 256) {
        sw1[i >> 7][i & 127] = w1[i];   // w1[j][c], j<32, c<128
        sw2[i >> 5][i & 31]  = w2[i];   // w2[c][j], c<128, j<32
    }

    cudaGridDependencySynchronize();    // wait for reduce_kernel's d_part

    for (int i = tid; i < 1024; i += 256) {
        const float* p = &d_part[i * BLKS_PER_CH];
        sg[i] = ((p[0] + p[1]) + (p[2] + p[3])) + p[4];
    }
    __syncthreads();

    // Stage 1: t1[b][j] = sum_c gap[b][c] * w1[j][c]
    int b = tid >> 5, j = tid & 31;
    float sacc = 0.f;
    #pragma unroll 8
    for (int c = 0; c < 128; c++) sacc += sg[b * 128 + c] * sw1[j][c];
    st1[tid] = sacc;
    __syncthreads();

    // Stage 2: att[b][c] = sigmoid(sum_j t1[b][j] * w2[c][j])
    for (int i = tid; i < 1024; i += 256) {
        int bb = i >> 7, cc = i & 127;
        float z = 0.f;
        #pragma unroll
        for (int jj = 0; jj < 32; jj++) z += st1[bb * 32 + jj] * sw2[cc][jj];
        d_att[i] = 1.f / (1.f + expf(-z));
    }
    __threadfence();
    __syncthreads();
    cudaTriggerProgrammaticLaunchCompletion();   // release scale at d_att store
}

// ---- Kernel 3: scale, 2 float4/thread, exact flat grid (PDL) -----------------
__global__ __launch_bounds__(256) void scale_kernel(const float4* __restrict__ x,
                                                    float4* __restrict__ out) {
    unsigned i0 = blockIdx.x * 512u + threadIdx.x;    // < 24,576,000 always
    unsigned i1 = i0 + 256u;
    float4 v0 = __ldcs(&x[i0]);          // both loads issue before the sync
    float4 v1 = __ldcs(&x[i1]);
    unsigned c0 = i0 / (unsigned)Q_PER_CH;
    unsigned c1 = i1 / (unsigned)Q_PER_CH;

    cudaGridDependencySynchronize();     // wait only for d_att

    float a0 = d_att[c0];
    float a1 = d_att[c1];
    v0.x *= a0; v0.y *= a0; v0.z *= a0; v0.w *= a0;
    v1.x *= a1; v1.y *= a1; v1.z *= a1; v1.w *= a1;
    __stcs(&out[i0], v0);
    __stcs(&out[i1], v1);
}

// ---- Launch ------------------------------------------------------------------
extern "C" void kernel_launch(void* const* d_in, const int* in_sizes, int n_in,
                              void* d_out, int out_size) {
    const float* x  = (const float*)d_in[0];
    const float* w1 = (const float*)d_in[1];
    const float* w2 = (const float*)d_in[2];
    float* out = (float*)d_out;

    reduce_kernel<<<N_CH * BLKS_PER_CH, 256>>>(reinterpret_cast<const float4*>(x));

    cudaLaunchAttribute attr[1];
    attr[0].id = cudaLaunchAttributeProgrammaticStreamSerialization;
    attr[0].val.programmaticStreamSerializationAllowed = 1;

    {   // mlp: PDL-overlapped with reduce
        cudaLaunchConfig_t cfg = {};
        cfg.gridDim = dim3(1, 1, 1);
        cfg.blockDim = dim3(256, 1, 1);
        cfg.dynamicSmemBytes = 0;
        cfg.stream = 0;
        cfg.attrs = attr;
        cfg.numAttrs = 1;
        cudaLaunchKernelEx(&cfg, mlp_kernel, w1, w2);
    }
    {   // scale: PDL-overlapped with mlp
        cudaLaunchConfig_t cfg = {};
        cfg.gridDim = dim3(TOTAL_Q4 / 512, 1, 1);     // 48000 blocks, no tail
        cfg.blockDim = dim3(256, 1, 1);
        cfg.dynamicSmemBytes = 0;
        cfg.stream = 0;
        cfg.attrs = attr;
        cfg.numAttrs = 1;
        cudaLaunchKernelEx(&cfg, scale_kernel,
                           reinterpret_cast<const float4*>(x),
                           reinterpret_cast<float4*>(out));
    }
}